// round 17
// baseline (speedup 1.0000x reference)
#include <cuda_runtime.h>
#include <cuda_bf16.h>
#include <cstdint>

// Problem constants
#define BB   2
#define LL   2048
#define DM   2048
#define NH   32
#define NKV  8
#define HD   64
#define MTOT (BB*LL)      // 4096 rows (b*l)
#define KVW  (NKV*HD)     // 512
#define QKVN (DM + 2*KVW) // 3072

// fp32 scratch consumed by attention
__device__ __align__(256) float g_q[(size_t)MTOT*DM];
__device__ __align__(256) float g_k[(size_t)MTOT*KVW];
__device__ __align__(256) float g_v[(size_t)MTOT*KVW];
// bf16 hi/lo split operands for the tensor-core GEMMs
__device__ __align__(256) __nv_bfloat16 x_hi[(size_t)MTOT*DM];
__device__ __align__(256) __nv_bfloat16 x_lo[(size_t)MTOT*DM];
__device__ __align__(256) __nv_bfloat16 wq_hi[(size_t)QKVN*DM];  // [N=3072][K=2048] (transposed)
__device__ __align__(256) __nv_bfloat16 wq_lo[(size_t)QKVN*DM];
__device__ __align__(256) __nv_bfloat16 wo_hi[(size_t)DM*DM];    // [N=2048][K=2048]
__device__ __align__(256) __nv_bfloat16 wo_lo[(size_t)DM*DM];
__device__ __align__(256) __nv_bfloat16 o_hi[(size_t)MTOT*DM];   // attention out, split
__device__ __align__(256) __nv_bfloat16 o_lo[(size_t)MTOT*DM];

// ---------------------------------------------------------------------------
// Helpers
// ---------------------------------------------------------------------------
__device__ __forceinline__ uint32_t smem_u32(const void* p) {
    uint32_t a;
    asm("{ .reg .u64 t; cvta.to.shared.u64 t, %1; cvt.u32.u64 %0, t; }"
        : "=r"(a) : "l"(p));
    return a;
}

__device__ __forceinline__ void ldm4(uint32_t addr, uint32_t* r) {
    asm volatile("ldmatrix.sync.aligned.m8n8.x4.shared.b16 {%0,%1,%2,%3}, [%4];"
        : "=r"(r[0]), "=r"(r[1]), "=r"(r[2]), "=r"(r[3]) : "r"(addr));
}
__device__ __forceinline__ void ldm4t(uint32_t addr, uint32_t* r) {
    asm volatile("ldmatrix.sync.aligned.m8n8.x4.trans.shared.b16 {%0,%1,%2,%3}, [%4];"
        : "=r"(r[0]), "=r"(r[1]), "=r"(r[2]), "=r"(r[3]) : "r"(addr));
}

// D += A(m16k16) * B(n8k16)^T, bf16 in, fp32 accum
__device__ __forceinline__ void mma16816(float* c, const uint32_t* a,
                                         uint32_t b0, uint32_t b1) {
    asm volatile(
        "mma.sync.aligned.m16n8k16.row.col.f32.bf16.bf16.f32 "
        "{%0,%1,%2,%3}, {%4,%5,%6,%7}, {%8,%9}, {%0,%1,%2,%3};"
        : "+f"(c[0]), "+f"(c[1]), "+f"(c[2]), "+f"(c[3])
        : "r"(a[0]), "r"(a[1]), "r"(a[2]), "r"(a[3]), "r"(b0), "r"(b1));
}

__device__ __forceinline__ void cpasync16(uint32_t saddr, const void* gaddr) {
    asm volatile("cp.async.cg.shared.global [%0], [%1], 16;"
                 :: "r"(saddr), "l"(gaddr) : "memory");
}
#define CP_COMMIT() asm volatile("cp.async.commit_group;" ::: "memory")
#define CP_WAIT0()  asm volatile("cp.async.wait_group 0;" ::: "memory")

__device__ __forceinline__ void split_hl(float v, unsigned short& h, unsigned short& l) {
    __nv_bfloat16 bh = __float2bfloat16_rn(v);
    h = __bfloat16_as_ushort(bh);
    float r = v - __bfloat162float(bh);
    l = __bfloat16_as_ushort(__float2bfloat16_rn(r));
}

// two floats -> packed bf16x2 hi + residual bf16x2 lo
__device__ __forceinline__ void hl2(float f0, float f1, uint32_t& h, uint32_t& l) {
    unsigned short h0, l0, h1, l1;
    split_hl(f0, h0, l0);
    split_hl(f1, h1, l1);
    h = (uint32_t)h0 | ((uint32_t)h1 << 16);
    l = (uint32_t)l0 | ((uint32_t)l1 << 16);
}

// ---------------------------------------------------------------------------
// Prep kernels (unchanged, verified)
// ---------------------------------------------------------------------------
__global__ __launch_bounds__(256)
void split_x_kernel(const float* __restrict__ x)
{
    size_t i4 = (size_t)blockIdx.x * 256 + threadIdx.x;   // one float4 each
    float4 v = *((const float4*)x + i4);
    unsigned short h0, l0, h1, l1, h2, l2, h3, l3;
    split_hl(v.x, h0, l0); split_hl(v.y, h1, l1);
    split_hl(v.z, h2, l2); split_hl(v.w, h3, l3);
    *(uint2*)&x_hi[i4 * 4] = make_uint2((uint32_t)h0 | ((uint32_t)h1 << 16),
                                        (uint32_t)h2 | ((uint32_t)h3 << 16));
    *(uint2*)&x_lo[i4 * 4] = make_uint2((uint32_t)l0 | ((uint32_t)l1 << 16),
                                        (uint32_t)l2 | ((uint32_t)l3 << 16));
}

// Transpose W[K][N] -> T[N][K] with hi/lo split. block (32,8), 32x32 tiles.
__global__ __launch_bounds__(256)
void wsplit_kernel(const float* __restrict__ W, __nv_bfloat16* __restrict__ Thi,
                   __nv_bfloat16* __restrict__ Tlo, int K, int N)
{
    __shared__ float tile[32][33];
    int n0 = blockIdx.x * 32, k0 = blockIdx.y * 32;
    int tx = threadIdx.x, ty = threadIdx.y;
#pragma unroll
    for (int i = 0; i < 4; i++)
        tile[ty + 8 * i][tx] = W[(size_t)(k0 + ty + 8 * i) * N + n0 + tx];
    __syncthreads();
#pragma unroll
    for (int i = 0; i < 4; i++) {
        int n = n0 + ty + 8 * i, k = k0 + tx;
        unsigned short h, l;
        split_hl(tile[tx][ty + 8 * i], h, l);
        Thi[(size_t)n * K + k] = __ushort_as_bfloat16(h);
        Tlo[(size_t)n * K + k] = __ushort_as_bfloat16(l);
    }
}

// ---------------------------------------------------------------------------
// bf16x3 GEMM on mma.sync, cp.async 2-stage, CTA tile 256x128.
// 8 warps as 4x2; warp tile 64x64 (ldm/mma ratio 0.167 vs 0.25 before —
// attacks the LDSM structural-floor feed limit seen at tensor=47.5%).
// ---------------------------------------------------------------------------
#define KS 40                 // halves per smem row (80B, 16B-aligned)
#define BK 32
#define NTCH (2048/BK)        // 64 k-chunks
#define AARR (256*KS*2)       // bytes per A operand array (20480)
#define BARR (128*KS*2)       // bytes per B operand array (10240)
#define STGB (2*AARR+2*BARR)  // bytes per stage (61440)
#define GSMEM (2*STGB)        // total dynamic smem (122880)

template<int SPLIT>
__global__ __launch_bounds__(256)
void hmma_gemm(const __nv_bfloat16* __restrict__ Ahi, const __nv_bfloat16* __restrict__ Alo,
               const __nv_bfloat16* __restrict__ Bhi, const __nv_bfloat16* __restrict__ Blo,
               float* __restrict__ C, int N)
{
    extern __shared__ __nv_bfloat16 smd[];
    const uint32_t base = smem_u32(smd);

    const int t    = threadIdx.x;
    const int lane = t & 31, wid = t >> 5;
    const int wm = wid >> 1, wn = wid & 1;      // 4x2 warp grid, warp tile 64x64
    const int m0 = blockIdx.y * 256;
    const int n0 = blockIdx.x * 128;

    const int lrow = lane & 15, lhalf = lane >> 4;

    uint32_t aOff[4], bOff[4];
#pragma unroll
    for (int mt = 0; mt < 4; mt++)
        aOff[mt] = (uint32_t)(wm * 64 + mt * 16 + lrow) * (KS * 2) + lhalf * 16;
#pragma unroll
    for (int np = 0; np < 4; np++)
        bOff[np] = (uint32_t)(wn * 64 + np * 16 + lrow) * (KS * 2) + lhalf * 16;

    const int grow = t >> 2, gq = t & 3;        // grow 0..63, 16B chunk gq
    const __nv_bfloat16* Aps[2] = { Ahi + (size_t)m0 * 2048, Alo + (size_t)m0 * 2048 };
    const __nv_bfloat16* Bps[2] = { Bhi + (size_t)n0 * 2048, Blo + (size_t)n0 * 2048 };

    float acc[4][8][4];
#pragma unroll
    for (int mt = 0; mt < 4; mt++)
#pragma unroll
        for (int nt = 0; nt < 8; nt++)
#pragma unroll
            for (int r = 0; r < 4; r++) acc[mt][nt][r] = 0.f;

    // fill one stage with chunk at k0
    auto fill = [&](uint32_t sb, int k0) {
#pragma unroll
        for (int a = 0; a < 2; a++) {
#pragma unroll
            for (int rr = 0; rr < 4; rr++) {
                int row = grow + rr * 64;
                cpasync16(sb + a * AARR + (uint32_t)(row * KS + gq * 8) * 2,
                          Aps[a] + (size_t)row * 2048 + k0 + gq * 8);
            }
        }
#pragma unroll
        for (int b = 0; b < 2; b++) {
#pragma unroll
            for (int rr = 0; rr < 2; rr++) {
                int row = grow + rr * 64;
                cpasync16(sb + 2 * AARR + b * BARR + (uint32_t)(row * KS + gq * 8) * 2,
                          Bps[b] + (size_t)row * 2048 + k0 + gq * 8);
            }
        }
        CP_COMMIT();
    };

    fill(base, 0);
    CP_WAIT0();
    __syncthreads();

    for (int c = 0; c < NTCH; c++) {
        if (c + 1 < NTCH)
            fill(base + ((c + 1) & 1) * STGB, (c + 1) * BK);  // overlaps compute

        const uint32_t sb = base + (c & 1) * STGB;
        const uint32_t sAh = sb, sAl = sb + AARR;
        const uint32_t sBh = sb + 2 * AARR, sBl = sb + 2 * AARR + BARR;
#pragma unroll
        for (int ks = 0; ks < 2; ks++) {
            const uint32_t kb = ks * 32;
            uint32_t Ah[4][4], Al[4][4], Bf[4][4];
            // hi * hi
#pragma unroll
            for (int mt = 0; mt < 4; mt++) ldm4(sAh + aOff[mt] + kb, Ah[mt]);
#pragma unroll
            for (int np = 0; np < 4; np++) ldm4(sBh + bOff[np] + kb, Bf[np]);
#pragma unroll
            for (int mt = 0; mt < 4; mt++)
#pragma unroll
                for (int nt = 0; nt < 8; nt++)
                    mma16816(acc[mt][nt], Ah[mt],
                             Bf[nt >> 1][nt & 1], Bf[nt >> 1][2 + (nt & 1)]);
            // lo * hi (reuse Bf)
#pragma unroll
            for (int mt = 0; mt < 4; mt++) ldm4(sAl + aOff[mt] + kb, Al[mt]);
#pragma unroll
            for (int mt = 0; mt < 4; mt++)
#pragma unroll
                for (int nt = 0; nt < 8; nt++)
                    mma16816(acc[mt][nt], Al[mt],
                             Bf[nt >> 1][nt & 1], Bf[nt >> 1][2 + (nt & 1)]);
            // hi * lo (reload Bf with Blo, reuse Ah)
#pragma unroll
            for (int np = 0; np < 4; np++) ldm4(sBl + bOff[np] + kb, Bf[np]);
#pragma unroll
            for (int mt = 0; mt < 4; mt++)
#pragma unroll
                for (int nt = 0; nt < 8; nt++)
                    mma16816(acc[mt][nt], Ah[mt],
                             Bf[nt >> 1][nt & 1], Bf[nt >> 1][2 + (nt & 1)]);
        }

        if (c + 1 < NTCH) {
            CP_WAIT0();
            __syncthreads();
        }
    }

    float* dst; int ldd, cb;
    if (SPLIT == 0)               { dst = C;   ldd = N;   cb = n0; }
    else if (n0 < NH * HD)        { dst = g_q; ldd = DM;  cb = n0; }
    else if (n0 < (NH+NKV) * HD)  { dst = g_k; ldd = KVW; cb = n0 - NH*HD; }
    else                          { dst = g_v; ldd = KVW; cb = n0 - (NH+NKV)*HD; }

    const int erow = lane >> 2, ecol = (lane & 3) * 2;
#pragma unroll
    for (int mt = 0; mt < 4; mt++) {
        const int r0 = m0 + wm * 64 + mt * 16 + erow;
#pragma unroll
        for (int nt = 0; nt < 8; nt++) {
            const int cc = cb + wn * 64 + nt * 8 + ecol;
            *(float2*)&dst[(size_t)r0 * ldd + cc]       =
                make_float2(acc[mt][nt][0], acc[mt][nt][1]);
            *(float2*)&dst[(size_t)(r0 + 8) * ldd + cc] =
                make_float2(acc[mt][nt][2], acc[mt][nt][3]);
        }
    }
}

// ---------------------------------------------------------------------------
// Flash attention on HMMA (bf16 hi/lo x3) — verified in R13, unchanged.
// ---------------------------------------------------------------------------
#define ATS 72   // bf16 halves per smem row (144B; rows stagger 16B in banks)

__global__ __launch_bounds__(256)
void attn_kernel()
{
    extern __shared__ __nv_bfloat16 smb[];
    __nv_bfloat16* Qh = smb;                 // [128][ATS]
    __nv_bfloat16* Ql = Qh + 128 * ATS;
    __nv_bfloat16* Kh = Ql + 128 * ATS;      // [64][ATS]
    __nv_bfloat16* Kl = Kh + 64 * ATS;
    __nv_bfloat16* Vh = Kl + 64 * ATS;
    __nv_bfloat16* Vl = Vh + 64 * ATS;

    const int t = threadIdx.x;
    const int lane = t & 31, w = t >> 5;
    const int lrow = lane & 15, lhalf = lane >> 4;
    const int erow = lane >> 2, ecol = (lane & 3) * 2;

    const int qb = (int)gridDim.x - 1 - (int)blockIdx.x;  // big blocks first
    const int bH = blockIdx.y;
    const int bb = bH >> 5;
    const int H  = bH & 31;
    const int hk = H & 7;
    const int qg0 = qb * 128;

    const float* Qg = g_q + (size_t)bb * LL * DM  + (size_t)H  * LL * HD;
    const float* Kg = g_k + (size_t)bb * LL * KVW + (size_t)hk * LL * HD;
    const float* Vg = g_v + (size_t)bb * LL * KVW + (size_t)hk * LL * HD;

    // fill Q smem (hi/lo): 128x64 fp32 -> 32 floats per thread
#pragma unroll
    for (int s = 0; s < 8; s++) {
        int idx = t + 256 * s;                 // 0..2047 float4s
        int row = idx >> 4, d4 = (idx & 15) << 2;
        float4 v = *(const float4*)&Qg[(size_t)(qg0 + row) * HD + d4];
        unsigned short h0,l0,h1,l1,h2,l2,h3,l3;
        split_hl(v.x, h0, l0); split_hl(v.y, h1, l1);
        split_hl(v.z, h2, l2); split_hl(v.w, h3, l3);
        *(uint2*)&Qh[row * ATS + d4] = make_uint2((uint32_t)h0 | ((uint32_t)h1 << 16),
                                                  (uint32_t)h2 | ((uint32_t)h3 << 16));
        *(uint2*)&Ql[row * ATS + d4] = make_uint2((uint32_t)l0 | ((uint32_t)l1 << 16),
                                                  (uint32_t)l2 | ((uint32_t)l3 << 16));
    }
    __syncthreads();

    // Q fragments (held in regs for the whole kernel)
    uint32_t Qf[2][4][4];
    {
        uint32_t qoff = (uint32_t)(w * 16 + lrow) * (ATS * 2) + lhalf * 16;
        uint32_t qha = smem_u32(Qh), qla = smem_u32(Ql);
#pragma unroll
        for (int ks = 0; ks < 4; ks++) {
            ldm4(qha + qoff + ks * 32, Qf[0][ks]);
            ldm4(qla + qoff + ks * 32, Qf[1][ks]);
        }
    }

    const uint32_t kha = smem_u32(Kh), kla = smem_u32(Kl);
    const uint32_t vha = smem_u32(Vh), vla = smem_u32(Vl);
    const uint32_t koff = (uint32_t)lrow * (ATS * 2) + lhalf * 16;

    float m0 = -1e30f, m1 = -1e30f, l0 = 0.f, l1 = 0.f;
    float O[8][4];
#pragma unroll
    for (int dt = 0; dt < 8; dt++)
#pragma unroll
        for (int r = 0; r < 4; r++) O[dt][r] = 0.f;

    const int wrow = qg0 + w * 16;          // warp's first row
    const int r0g = wrow + erow;            // this lane's rows
    const int r1g = r0g + 8;
    const int nkb = 2 * qb + 2;

    for (int kb = 0; kb < nkb; kb++) {
        const int j0 = kb * 64;
        __syncthreads();
        // fill K,V hi/lo: 64x64 fp32 each -> 4 float4 per thread per tensor
#pragma unroll
        for (int s = 0; s < 4; s++) {
            int idx = t + 256 * s;
            int row = idx >> 4, d4 = (idx & 15) << 2;
            float4 kv = *(const float4*)&Kg[(size_t)(j0 + row) * HD + d4];
            unsigned short h0,lw0,h1,lw1,h2,lw2,h3,lw3;
            split_hl(kv.x, h0, lw0); split_hl(kv.y, h1, lw1);
            split_hl(kv.z, h2, lw2); split_hl(kv.w, h3, lw3);
            *(uint2*)&Kh[row * ATS + d4] = make_uint2((uint32_t)h0 | ((uint32_t)h1 << 16),
                                                      (uint32_t)h2 | ((uint32_t)h3 << 16));
            *(uint2*)&Kl[row * ATS + d4] = make_uint2((uint32_t)lw0 | ((uint32_t)lw1 << 16),
                                                      (uint32_t)lw2 | ((uint32_t)lw3 << 16));
            float4 vv = *(const float4*)&Vg[(size_t)(j0 + row) * HD + d4];
            split_hl(vv.x, h0, lw0); split_hl(vv.y, h1, lw1);
            split_hl(vv.z, h2, lw2); split_hl(vv.w, h3, lw3);
            *(uint2*)&Vh[row * ATS + d4] = make_uint2((uint32_t)h0 | ((uint32_t)h1 << 16),
                                                      (uint32_t)h2 | ((uint32_t)h3 << 16));
            *(uint2*)&Vl[row * ATS + d4] = make_uint2((uint32_t)lw0 | ((uint32_t)lw1 << 16),
                                                      (uint32_t)lw2 | ((uint32_t)lw3 << 16));
        }
        __syncthreads();

        if (j0 > wrow + 15) continue;       // fully masked for this warp
        const bool pmask = (j0 + 63 > wrow);

        // ---- S = Q K^T (hi*hi + lo*hi + hi*lo) ----
        float Sf[8][4];
#pragma unroll
        for (int nt = 0; nt < 8; nt++)
#pragma unroll
            for (int r = 0; r < 4; r++) Sf[nt][r] = 0.f;

#pragma unroll
        for (int ks = 0; ks < 4; ks++) {
            uint32_t Khf[4][4], Klf[4][4];
#pragma unroll
            for (int g = 0; g < 4; g++) {
                ldm4(kha + (uint32_t)g * 16 * (ATS * 2) + koff + ks * 32, Khf[g]);
                ldm4(kla + (uint32_t)g * 16 * (ATS * 2) + koff + ks * 32, Klf[g]);
            }
#pragma unroll
            for (int nt = 0; nt < 8; nt++) {
                uint32_t b0h = Khf[nt >> 1][nt & 1], b1h = Khf[nt >> 1][2 + (nt & 1)];
                uint32_t b0l = Klf[nt >> 1][nt & 1], b1l = Klf[nt >> 1][2 + (nt & 1)];
                mma16816(Sf[nt], Qf[0][ks], b0h, b1h);
                mma16816(Sf[nt], Qf[1][ks], b0h, b1h);
                mma16816(Sf[nt], Qf[0][ks], b0l, b1l);
            }
        }

        // ---- online softmax in fragment space ----
        float mx0 = -1e30f, mx1 = -1e30f;
#pragma unroll
        for (int nt = 0; nt < 8; nt++) {
#pragma unroll
            for (int v = 0; v < 2; v++) {
                float s = Sf[nt][v] * 0.125f;
                if (pmask && (j0 + nt * 8 + ecol + v > r0g)) s = -1e30f;
                Sf[nt][v] = s;
                mx0 = fmaxf(mx0, s);
            }
#pragma unroll
            for (int v = 2; v < 4; v++) {
                float s = Sf[nt][v] * 0.125f;
                if (pmask && (j0 + nt * 8 + ecol + v - 2 > r1g)) s = -1e30f;
                Sf[nt][v] = s;
                mx1 = fmaxf(mx1, s);
            }
        }
        mx0 = fmaxf(mx0, __shfl_xor_sync(0xffffffffu, mx0, 1));
        mx0 = fmaxf(mx0, __shfl_xor_sync(0xffffffffu, mx0, 2));
        mx1 = fmaxf(mx1, __shfl_xor_sync(0xffffffffu, mx1, 1));
        mx1 = fmaxf(mx1, __shfl_xor_sync(0xffffffffu, mx1, 2));

        float mn0 = fmaxf(m0, mx0), mn1 = fmaxf(m1, mx1);
        float a0 = __expf(m0 - mn0), a1 = __expf(m1 - mn1);
        m0 = mn0; m1 = mn1;
#pragma unroll
        for (int dt = 0; dt < 8; dt++) {
            O[dt][0] *= a0; O[dt][1] *= a0;
            O[dt][2] *= a1; O[dt][3] *= a1;
        }
        float rs0 = 0.f, rs1 = 0.f;
#pragma unroll
        for (int nt = 0; nt < 8; nt++) {
#pragma unroll
            for (int v = 0; v < 2; v++) {
                float p = __expf(Sf[nt][v] - mn0);
                Sf[nt][v] = p; rs0 += p;
            }
#pragma unroll
            for (int v = 2; v < 4; v++) {
                float p = __expf(Sf[nt][v] - mn1);
                Sf[nt][v] = p; rs1 += p;
            }
        }
        rs0 += __shfl_xor_sync(0xffffffffu, rs0, 1);
        rs0 += __shfl_xor_sync(0xffffffffu, rs0, 2);
        rs1 += __shfl_xor_sync(0xffffffffu, rs1, 1);
        rs1 += __shfl_xor_sync(0xffffffffu, rs1, 2);
        l0 = l0 * a0 + rs0;
        l1 = l1 * a1 + rs1;

        // ---- O += P V (hi*hi + lo*hi + hi*lo) ----
#pragma unroll
        for (int js = 0; js < 4; js++) {
            uint32_t pah[4], pal[4];
            hl2(Sf[2*js][0],   Sf[2*js][1],   pah[0], pal[0]);
            hl2(Sf[2*js][2],   Sf[2*js][3],   pah[1], pal[1]);
            hl2(Sf[2*js+1][0], Sf[2*js+1][1], pah[2], pal[2]);
            hl2(Sf[2*js+1][2], Sf[2*js+1][3], pah[3], pal[3]);

            uint32_t Vhf[4][4], Vlf[4][4];
            const uint32_t voff = (uint32_t)(js * 16 + lrow) * (ATS * 2) + lhalf * 16;
#pragma unroll
            for (int dh = 0; dh < 4; dh++) {
                ldm4t(vha + voff + dh * 32, Vhf[dh]);
                ldm4t(vla + voff + dh * 32, Vlf[dh]);
            }
#pragma unroll
            for (int dt = 0; dt < 8; dt++) {
                const int dh = dt >> 1, o = (dt & 1) * 2;
                uint32_t b0h = Vhf[dh][o], b1h = Vhf[dh][o + 1];
                uint32_t b0l = Vlf[dh][o], b1l = Vlf[dh][o + 1];
                mma16816(O[dt], pah, b0h, b1h);
                mma16816(O[dt], pal, b0h, b1h);
                mma16816(O[dt], pah, b0l, b1l);
            }
        }
    }

    // epilogue: O /= l, hi/lo bf16 split, (b, l, (g h d)) layout
    float inv0 = 1.f / l0, inv1 = 1.f / l1;
#pragma unroll
    for (int dt = 0; dt < 8; dt++) {
        uint32_t h01, l01, h23, l23;
        hl2(O[dt][0] * inv0, O[dt][1] * inv0, h01, l01);
        hl2(O[dt][2] * inv1, O[dt][3] * inv1, h23, l23);
        size_t base0 = (size_t)(bb * LL + r0g) * DM + H * HD + dt * 8 + ecol;
        size_t base1 = (size_t)(bb * LL + r1g) * DM + H * HD + dt * 8 + ecol;
        *(uint32_t*)&o_hi[base0] = h01;
        *(uint32_t*)&o_lo[base0] = l01;
        *(uint32_t*)&o_hi[base1] = h23;
        *(uint32_t*)&o_lo[base1] = l23;
    }
}

// ---------------------------------------------------------------------------
extern "C" void kernel_launch(void* const* d_in, const int* in_sizes, int n_in,
                              void* d_out, int out_size)
{
    (void)in_sizes; (void)n_in; (void)out_size;
    const float* x    = (const float*)d_in[0];
    // d_in[1] (additive causal mask) reproduced exactly by in-kernel masking.
    const float* Wqkv = (const float*)d_in[2];
    const float* Wout = (const float*)d_in[3];
    float* out = (float*)d_out;

    __nv_bfloat16 *p_xh, *p_xl, *p_qh, *p_ql, *p_oh, *p_ol, *p_ohh, *p_oll;
    cudaGetSymbolAddress((void**)&p_xh, x_hi);
    cudaGetSymbolAddress((void**)&p_xl, x_lo);
    cudaGetSymbolAddress((void**)&p_qh, wq_hi);
    cudaGetSymbolAddress((void**)&p_ql, wq_lo);
    cudaGetSymbolAddress((void**)&p_oh, wo_hi);
    cudaGetSymbolAddress((void**)&p_ol, wo_lo);
    cudaGetSymbolAddress((void**)&p_ohh, o_hi);
    cudaGetSymbolAddress((void**)&p_oll, o_lo);

    cudaFuncSetAttribute(hmma_gemm<1>, cudaFuncAttributeMaxDynamicSharedMemorySize, GSMEM);
    cudaFuncSetAttribute(hmma_gemm<0>, cudaFuncAttributeMaxDynamicSharedMemorySize, GSMEM);

    // 0) prep: split/transposes
    split_x_kernel<<<(MTOT * DM / 4) / 256, 256>>>(x);
    wsplit_kernel<<<dim3(QKVN / 32, DM / 32), dim3(32, 8)>>>(Wqkv, p_qh, p_ql, DM, QKVN);
    wsplit_kernel<<<dim3(DM / 32, DM / 32), dim3(32, 8)>>>(Wout, p_oh, p_ol, DM, DM);

    // 1) QKV projection (HMMA 256x128 tiles), split into g_q/g_k/g_v
    hmma_gemm<1><<<dim3(QKVN / 128, MTOT / 256), 256, GSMEM>>>(p_xh, p_xl, p_qh, p_ql,
                                                               nullptr, QKVN);

    // 2) attention (HMMA flash)
    const int smbytes = (2 * 128 + 4 * 64) * ATS * (int)sizeof(__nv_bfloat16);
    cudaFuncSetAttribute(attn_kernel, cudaFuncAttributeMaxDynamicSharedMemorySize, smbytes);
    attn_kernel<<<dim3(LL / 128, BB * NH), 256, smbytes>>>();

    // 3) output projection (HMMA 256x128 tiles)
    hmma_gemm<0><<<dim3(DM / 128, MTOT / 256), 256, GSMEM>>>(p_ohh, p_oll, p_oh, p_ol,
                                                             out, DM);
}